// round 10
// baseline (speedup 1.0000x reference)
#include <cuda_runtime.h>
#include <cuda_fp16.h>
#include <cstdint>

#define BB 8192
#define TT 96
#define FF 64
#define HH 256
#define KTOT 320

// ---------------- static device buffers ----------------
__device__ __align__(256) __half g_Bt[1024 * KTOT];              // weights hi [n*320+k]
__device__ __align__(256) __half g_hP[2][2][(size_t)BB * HH];    // [parity][hi/lo]
__device__ __align__(256) __half g_f16[(size_t)BB * TT * FF];    // features (hi only)
__device__ float g_prevbuf[3][BB];
__device__ float g_epi[HH * 8];  // {k0z,k0r,k0h,bz,br,bxh,bhh,dw}

// ---------------- helpers ----------------
static __device__ __forceinline__ uint32_t smem_u32(const void* p) {
    uint32_t a;
    asm("{ .reg .u64 t; cvta.to.shared.u64 t, %1; cvt.u32.u64 %0, t; }"
        : "=r"(a) : "l"(p));
    return a;
}
static __device__ __forceinline__ void cpasync16(uint32_t dst, const void* src) {
    asm volatile("cp.async.cg.shared.global [%0], [%1], 16;"
                 :: "r"(dst), "l"(src) : "memory");
}
static __device__ __forceinline__ void ldm4(uint32_t* d, uint32_t a) {
    asm volatile("ldmatrix.sync.aligned.m8n8.x4.shared.b16 {%0,%1,%2,%3}, [%4];"
                 : "=r"(d[0]), "=r"(d[1]), "=r"(d[2]), "=r"(d[3]) : "r"(a));
}
static __device__ __forceinline__ void mmaf16(float* c, const uint32_t* a,
                                              uint32_t b0, uint32_t b1) {
    asm volatile(
        "mma.sync.aligned.m16n8k16.row.col.f32.f16.f16.f32 "
        "{%0,%1,%2,%3},{%4,%5,%6,%7},{%8,%9},{%0,%1,%2,%3};"
        : "+f"(c[0]), "+f"(c[1]), "+f"(c[2]), "+f"(c[3])
        : "r"(a[0]), "r"(a[1]), "r"(a[2]), "r"(a[3]), "r"(b0), "r"(b1));
}
__device__ __forceinline__ float sigf(float x) {
    return __fdividef(1.0f, 1.0f + __expf(-x));
}
__device__ __forceinline__ float tanhfast(float x) {
    return 1.0f - __fdividef(2.0f, __expf(2.0f * x) + 1.0f);
}
__device__ __forceinline__ float hfpart(uint32_t w, int hi) {
    __half_raw r;
    r.x = hi ? (unsigned short)(w >> 16) : (unsigned short)(w & 0xffff);
    return __half2float(__half(r));
}

// ---------------- prep kernels ----------------
__global__ void prep_feat(const float* __restrict__ f) {
    size_t i = (size_t)blockIdx.x * 256 + threadIdx.x;
    if (i >= (size_t)BB * TT * FF) return;
    g_f16[i] = __float2half_rn(f[i]);
}

__global__ void prep_B(const float* __restrict__ Kw, const float* __restrict__ Rw) {
    int idx = blockIdx.x * 256 + threadIdx.x;
    if (idx >= 1024 * KTOT) return;
    int n = idx / KTOT, k = idx % KTOT;
    int blk = n >> 6, w = n & 63, g = w >> 4, jl = w & 15;
    int j = blk * 16 + jl;
    float v = 0.f;
    if (k < HH) {
        if (g == 0) v = Rw[k * 768 + j];
        else if (g == 1) v = Rw[k * 768 + 256 + j];
        else if (g == 3) v = Rw[k * 768 + 512 + j];
    } else {
        int f = k - HH;
        if (g == 0) v = Kw[(1 + f) * 768 + j];
        else if (g == 1) v = Kw[(1 + f) * 768 + 256 + j];
        else if (g == 2) v = Kw[(1 + f) * 768 + 512 + j];
    }
    g_Bt[idx] = __float2half_rn(v);
}

__global__ void prep_init(const float* __restrict__ hs0, const float* __restrict__ inp0,
                          const float* __restrict__ Kw, const float* __restrict__ ib,
                          const float* __restrict__ rb, const float* __restrict__ dw,
                          const float* __restrict__ db) {
    size_t i = (size_t)blockIdx.x * 256 + threadIdx.x;
    if (i < (size_t)BB * HH) {
        float v = hs0[i];
        __half h = __float2half_rn(v);
        g_hP[0][0][i] = h;
        g_hP[0][1][i] = __float2half_rn(v - __half2float(h));
    }
    if (i < BB) {
        g_prevbuf[0][i] = inp0[i];
        g_prevbuf[1][i] = db[0];
        g_prevbuf[2][i] = db[0];
    }
    if (i < HH) {
        int j = (int)i;
        float* e = &g_epi[j * 8];
        e[0] = Kw[j];
        e[1] = Kw[256 + j];
        e[2] = Kw[512 + j];
        e[3] = ib[j] + rb[j];
        e[4] = ib[256 + j] + rb[256 + j];
        e[5] = ib[512 + j];
        e[6] = rb[512 + j];
        e[7] = dw[j];
    }
}

__global__ void fin_kernel(float* __restrict__ out) {
    int b = blockIdx.x * 256 + threadIdx.x;
    if (b < BB) out[(size_t)b * TT + (TT - 1)] = g_prevbuf[TT % 3][b];
}

// ---------------- step kernel ----------------
// smem: ring of 3 buffers, each A 16K | B 16K = 32K; + 1K epi
#define BUFSZ 32768
#define BOFF 16384
#define EPIOFF (3 * BUFSZ)
#define SMEM_TOTAL (EPIOFF + 1024)

__global__ __launch_bounds__(512, 2) void step_kernel(const float* __restrict__ db,
                                                      float* __restrict__ out, int t) {
    extern __shared__ char sm[];
    const uint32_t smb = smem_u32(sm);
    float* s_epi = (float*)(sm + EPIOFF);

    const int tid = threadIdx.x, lane = tid & 31, wid = tid >> 5;
    const int nt = blockIdx.x, mt = blockIdx.y;
    const int b0 = mt * 128;
    const int rd = t & 1, wr = rd ^ 1;
    const int wm = wid >> 1, wn = wid & 1;   // warp tile: 16m x 64n (16 warps)
    const int p0 = t % 3, p1 = (t + 1) % 3, p2 = (t + 2) % 3;

    // ---- cp.async loader (512 threads) ----
    auto issue = [&](int kc, uint32_t bb) {
#pragma unroll
        for (int i = 0; i < 2; i++) {  // A: 128 rows x 8 chunks of 16B
            int idx = tid + i * 512;
            int r = idx >> 3, c = idx & 7;
            uint32_t dst = bb + r * 128 + ((c ^ (r & 7)) << 4);
            const __half* src;
            if (kc < 4)
                src = &g_hP[rd][0][(size_t)(b0 + r) * HH + kc * 64 + c * 8];
            else
                src = &g_f16[((size_t)(b0 + r) * TT + t) * FF + c * 8];
            cpasync16(dst, src);
        }
#pragma unroll
        for (int i = 0; i < 2; i++) {  // B: 128 rows x 8 chunks of 16B
            int idx = tid + i * 512;
            int r = idx >> 3, c = idx & 7;
            uint32_t dst = bb + BOFF + r * 128 + ((c ^ (r & 7)) << 4);
            cpasync16(dst, &g_Bt[(size_t)(nt * 128 + r) * KTOT + kc * 64 + c * 8]);
        }
        asm volatile("cp.async.commit_group;" ::: "memory");
    };

    // front-load the first two chunks before anything else
    issue(0, smb);
    issue(1, smb + BUFSZ);

    if (nt == 0 && tid < 128) {
        int b = b0 + tid;
        if (t > 0) out[(size_t)b * TT + (t - 1)] = g_prevbuf[p0][b];
        g_prevbuf[p2][b] = db[0];
    }
    if (tid < 256) s_epi[tid] = g_epi[nt * 256 + tid];

    float acc[8][4];
#pragma unroll
    for (int a = 0; a < 8; a++)
#pragma unroll
        for (int q = 0; q < 4; q++) acc[a][q] = 0.f;

    const int arow = wm * 16 + (lane & 15), asel = lane >> 4;
    const int bsub = lane >> 3, bl8 = lane & 7;
    const int brow0 = wn * 64 + ((bsub >> 1) << 3) + bl8, bsel = bsub & 1;

    for (int kc = 0; kc < 5; ++kc) {
        if (kc < 4)
            asm volatile("cp.async.wait_group 1;" ::: "memory");
        else
            asm volatile("cp.async.wait_group 0;" ::: "memory");
        __syncthreads();  // single barrier per chunk (ring-3 makes reuse safe)

        if (kc < 3) {
            static const uint32_t boffs[3] = {0, BUFSZ, 2 * BUFSZ};
            issue(kc + 2, smb + boffs[(kc + 2) % 3]);
        }

        const uint32_t bb = smb + (uint32_t)(kc % 3) * BUFSZ;
        const bool last = (kc == 4);
#pragma unroll
        for (int q = 0; q < 4; q++) {
            uint32_t afr[4];
            {
                int c = q * 2 + asel;
                ldm4(afr, bb + arow * 128 + ((c ^ (arow & 7)) << 4));
            }
#pragma unroll
            for (int p = 0; p < 4; p++) {
                if (last ? (p == 3) : (p == 2)) continue;
                int r = brow0 + p * 16;
                int c = q * 2 + bsel;
                uint32_t v[4];
                ldm4(v, bb + BOFF + r * 128 + ((c ^ (r & 7)) << 4));
                mmaf16(acc[2 * p], afr, v[0], v[1]);
                mmaf16(acc[2 * p + 1], afr, v[2], v[3]);
            }
        }
    }

    // ---- fused epilogue ----
    const int tq = lane & 3, tr = lane >> 2;
    const int jb = (nt * 2 + wn) * 16;
    float ep[2][2][8];
#pragma unroll
    for (int ah = 0; ah < 2; ah++)
#pragma unroll
        for (int i = 0; i < 2; i++) {
            int jl = wn * 16 + ah * 8 + 2 * tq + i;  // within CTA's 32 j
            float4 u0 = *(const float4*)&s_epi[jl * 8];
            float4 u1 = *(const float4*)&s_epi[jl * 8 + 4];
            ep[ah][i][0] = u0.x; ep[ah][i][1] = u0.y;
            ep[ah][i][2] = u0.z; ep[ah][i][3] = u0.w;
            ep[ah][i][4] = u1.x; ep[ah][i][5] = u1.y;
            ep[ah][i][6] = u1.z; ep[ah][i][7] = u1.w;
        }

#pragma unroll
    for (int rs = 0; rs < 2; rs++) {
        const int b = b0 + wm * 16 + tr + rs * 8;
        const float prev = g_prevbuf[p0][b];
        float dacc = 0.f;
#pragma unroll
        for (int ah = 0; ah < 2; ah++) {
            const int j0 = jb + ah * 8 + 2 * tq;
            uint32_t hw = *(const uint32_t*)&g_hP[rd][0][(size_t)b * HH + j0];
            uint32_t lw = *(const uint32_t*)&g_hP[rd][1][(size_t)b * HH + j0];
            float hn2[2];
#pragma unroll
            for (int i = 0; i < 2; i++) {
                const float* e = ep[ah][i];
                float cz = acc[0 + ah][rs * 2 + i] + prev * e[0] + e[3];
                float cr = acc[2 + ah][rs * 2 + i] + prev * e[1] + e[4];
                float cx = acc[4 + ah][rs * 2 + i] + prev * e[2] + e[5];
                float ch = acc[6 + ah][rs * 2 + i] + e[6];
                float z = sigf(cz), r = sigf(cr);
                float cand = tanhfast(cx + r * ch);
                float hold = hfpart(hw, i) + hfpart(lw, i);
                float hn = z * hold + (1.f - z) * cand;
                dacc += hn * e[7];
                hn2[i] = hn;
            }
            __half h0 = __float2half_rn(hn2[0]);
            __half h1 = __float2half_rn(hn2[1]);
            __half l0 = __float2half_rn(hn2[0] - __half2float(h0));
            __half l1 = __float2half_rn(hn2[1] - __half2float(h1));
            uint32_t uhi = (uint32_t)__half_as_ushort(h0) |
                           ((uint32_t)__half_as_ushort(h1) << 16);
            uint32_t ulo = (uint32_t)__half_as_ushort(l0) |
                           ((uint32_t)__half_as_ushort(l1) << 16);
            *(uint32_t*)&g_hP[wr][0][(size_t)b * HH + j0] = uhi;
            *(uint32_t*)&g_hP[wr][1][(size_t)b * HH + j0] = ulo;
        }
        dacc += __shfl_xor_sync(0xffffffffu, dacc, 1);
        dacc += __shfl_xor_sync(0xffffffffu, dacc, 2);
        if (tq == 0) atomicAdd(&g_prevbuf[p1][b], dacc);
    }
}

// ---------------- launch ----------------
extern "C" void kernel_launch(void* const* d_in, const int* in_sizes, int n_in,
                              void* d_out, int out_size) {
    const float* feat  = (const float*)d_in[0];
    const float* hs0   = (const float*)d_in[1];
    const float* inp0  = (const float*)d_in[2];
    const float* Kw    = (const float*)d_in[3];
    const float* Rw    = (const float*)d_in[4];
    const float* ibias = (const float*)d_in[5];
    const float* rbias = (const float*)d_in[6];
    const float* dw    = (const float*)d_in[7];
    const float* db    = (const float*)d_in[8];
    float* out = (float*)d_out;

    cudaFuncSetAttribute(step_kernel, cudaFuncAttributeMaxDynamicSharedMemorySize,
                         SMEM_TOTAL);

    size_t nf = (size_t)BB * TT * FF;
    prep_feat<<<(unsigned)((nf + 255) / 256), 256>>>(feat);
    prep_B<<<(1024 * KTOT + 255) / 256, 256>>>(Kw, Rw);
    prep_init<<<(BB * HH + 255) / 256, 256>>>(hs0, inp0, Kw, ibias, rbias, dw, db);

    dim3 grid(8, 64);
    for (int t = 0; t < TT; ++t)
        step_kernel<<<grid, 512, SMEM_TOTAL>>>(db, out, t);

    fin_kernel<<<(BB + 255) / 256, 256>>>(out);
}

// round 12
// speedup vs baseline: 1.3496x; 1.3496x over previous
#include <cuda_runtime.h>
#include <cuda_fp16.h>
#include <cstdint>

#define BB 8192
#define TT 96
#define FF 64
#define HH 256

// ---------------- static device buffers ----------------
// Dense weights: [10 chunks][384 rows][64 k] fp16. chunk = pair*5+kc.
// row d = blk_l*48 + slot; j = pair*128 + blk_l*16 + (slot%16);
// slot/16: 0=z,1=r,2=hh(kc<4)/xh(kc==4). k = kc*64+kk (kc<4: Rw; kc==4: Kw[1+kk]).
__device__ __align__(256) __half g_W[10 * 384 * 64];
__device__ __align__(256) __half g_f16[(size_t)BB * TT * FF];  // features fp16
__device__ float g_epi[HH * 8];  // {k0z,k0r,k0h,bz,br,bxh,bhh,dw}

// ---------------- helpers ----------------
static __device__ __forceinline__ uint32_t smem_u32(const void* p) {
    uint32_t a;
    asm("{ .reg .u64 t; cvta.to.shared.u64 t, %1; cvt.u32.u64 %0, t; }"
        : "=r"(a) : "l"(p));
    return a;
}
static __device__ __forceinline__ void cpasync16(uint32_t dst, const void* src) {
    asm volatile("cp.async.cg.shared.global [%0], [%1], 16;"
                 :: "r"(dst), "l"(src) : "memory");
}
static __device__ __forceinline__ void ldm4(uint32_t* d, uint32_t a) {
    asm volatile("ldmatrix.sync.aligned.m8n8.x4.shared.b16 {%0,%1,%2,%3}, [%4];"
                 : "=r"(d[0]), "=r"(d[1]), "=r"(d[2]), "=r"(d[3]) : "r"(a));
}
static __device__ __forceinline__ void mmaf16(float* c, const uint32_t* a,
                                              uint32_t b0, uint32_t b1) {
    asm volatile(
        "mma.sync.aligned.m16n8k16.row.col.f32.f16.f16.f32 "
        "{%0,%1,%2,%3},{%4,%5,%6,%7},{%8,%9},{%0,%1,%2,%3};"
        : "+f"(c[0]), "+f"(c[1]), "+f"(c[2]), "+f"(c[3])
        : "r"(a[0]), "r"(a[1]), "r"(a[2]), "r"(a[3]), "r"(b0), "r"(b1));
}
__device__ __forceinline__ float sigf(float x) {
    return __fdividef(1.0f, 1.0f + __expf(-x));
}
__device__ __forceinline__ float tanhfast(float x) {
    return 1.0f - __fdividef(2.0f, __expf(2.0f * x) + 1.0f);
}
__device__ __forceinline__ float hfpart(uint32_t w, int hi) {
    __half_raw r;
    r.x = hi ? (unsigned short)(w >> 16) : (unsigned short)(w & 0xffff);
    return __half2float(__half(r));
}

// ---------------- prep kernels ----------------
__global__ void prep_feat(const float* __restrict__ f) {
    size_t i = (size_t)blockIdx.x * 256 + threadIdx.x;
    if (i >= (size_t)BB * TT * FF) return;
    g_f16[i] = __float2half_rn(f[i]);
}

__global__ void prep_W(const float* __restrict__ Kw, const float* __restrict__ Rw) {
    int idx = blockIdx.x * 256 + threadIdx.x;
    if (idx >= 10 * 384 * 64) return;
    int kk = idx & 63;
    int d = (idx >> 6) % 384;
    int c10 = idx / (384 * 64);
    int pair = c10 / 5, kc = c10 % 5;
    int blk_l = d / 48, slot = d % 48;
    int gate = slot >> 4, jl = slot & 15;
    int j = pair * 128 + blk_l * 16 + jl;
    int off = (gate == 0) ? 0 : (gate == 1) ? 256 : 512;
    float v;
    if (kc < 4) v = Rw[(kc * 64 + kk) * 768 + off + j];
    else        v = Kw[(1 + kk) * 768 + off + j];
    g_W[idx] = __float2half_rn(v);
}

__global__ void prep_epi(const float* __restrict__ Kw, const float* __restrict__ ib,
                         const float* __restrict__ rb, const float* __restrict__ dw) {
    int j = threadIdx.x;
    float* e = &g_epi[j * 8];
    e[0] = Kw[j];
    e[1] = Kw[256 + j];
    e[2] = Kw[512 + j];
    e[3] = ib[j] + rb[j];
    e[4] = ib[256 + j] + rb[256 + j];
    e[5] = ib[512 + j];
    e[6] = rb[512 + j];
    e[7] = dw[j];
}

// ---------------- persistent scan kernel ----------------
// SMEM: ring 2x48K | Apanels 2x5x8K (0-3 h, 4 feat) | h_lo 32K | epi 8K | prev 2x64f | dacc 64f
#define RING_OFF 0
#define APAN_OFF 98304
#define LO_OFF   180224
#define EPI_OFF  212992
#define PREV_OFF 221184
#define DACC_OFF 221696
#define SMEM_TOTAL 221952

__global__ __launch_bounds__(512, 1) void scan_kernel(
    const float* __restrict__ hs0, const float* __restrict__ inp0,
    const float* __restrict__ db, float* __restrict__ out) {
    extern __shared__ char sm[];
    const uint32_t smb = smem_u32(sm);
    float* s_epi = (float*)(sm + EPI_OFF);
    float* s_prev = (float*)(sm + PREV_OFF);   // [2][64]
    float* s_dacc = (float*)(sm + DACC_OFF);   // [64]
    __half* s_lo = (__half*)(sm + LO_OFF);     // [64][256]

    const int tid = threadIdx.x, lane = tid & 31, wid = tid >> 5;
    const int b0 = blockIdx.x * 64;
    const int wm = wid >> 3, wn = wid & 7;     // 2m x 8n warps; warp = 32m x 48n
    const int tq = lane & 3, tr = lane >> 2;

    const int arow = wm * 32 + (lane & 15), asel = lane >> 4;
    const int bsub = lane >> 3, bl8 = lane & 7;
    const int brow0 = wn * 48 + ((bsub >> 1) << 3) + bl8, bsel = bsub & 1;

    // ---- weight-chunk loader (48KB) ; feat(t+1) piggybacks on chunk c%10==7 ----
    auto issue = [&](int c) {
        if (c >= TT * 10) return;
        const int cm = c % 10;
        const uint32_t base = smb + RING_OFF + (uint32_t)(c & 1) * 49152u;
        const __half* wsrc = &g_W[cm * (384 * 64)];
#pragma unroll
        for (int i = 0; i < 6; i++) {
            int u = tid + i * 512;
            int r = u >> 3, cc = u & 7;
            cpasync16(base + r * 128 + ((cc ^ (r & 7)) << 4), wsrc + r * 64 + cc * 8);
        }
        if (cm == 7) {
            int tn = c / 10 + 1;
            if (tn < TT) {
                int r = tid >> 3, cc = tid & 7;
                uint32_t fb = smb + APAN_OFF + (uint32_t)(tn & 1) * 40960u + 4u * 8192u;
                cpasync16(fb + r * 128 + ((cc ^ (r & 7)) << 4),
                          &g_f16[((size_t)(b0 + r) * TT + tn) * FF + cc * 8]);
            }
        }
        asm volatile("cp.async.commit_group;" ::: "memory");
    };

    issue(0);

    // ---- init: h -> panels[0] + lo ; feat(0) ; epi ; prev ----
    for (int idx = tid; idx < 64 * 256; idx += 512) {
        int m = idx >> 8, j = idx & 255;
        float v = hs0[(size_t)(b0 + m) * HH + j];
        __half hi = __float2half_rn(v);
        s_lo[m * 256 + j] = __float2half_rn(v - __half2float(hi));
        int cc = (j & 63) >> 3;
        *(__half*)(sm + APAN_OFF + (j >> 6) * 8192 + m * 128 +
                   ((cc ^ (m & 7)) << 4) + (j & 7) * 2) = hi;
    }
    {   // feat t=0 (plain copy; g_f16 already fp16)
        int r = tid >> 3, cc = tid & 7;
        *(uint4*)(sm + APAN_OFF + 4 * 8192 + r * 128 + ((cc ^ (r & 7)) << 4)) =
            *(const uint4*)&g_f16[((size_t)(b0 + r) * TT) * FF + cc * 8];
    }
    for (int i = tid; i < 2048; i += 512) s_epi[i] = g_epi[i];
    if (tid < 64) {
        s_prev[tid] = inp0[b0 + tid];
        s_dacc[tid] = 0.f;
    }
    __syncthreads();

    float acc[2][6][4], accx[2][2][4];
#pragma unroll
    for (int mi = 0; mi < 2; mi++) {
#pragma unroll
        for (int a = 0; a < 6; a++)
#pragma unroll
            for (int q = 0; q < 4; q++) acc[mi][a][q] = 0.f;
#pragma unroll
        for (int a = 0; a < 2; a++)
#pragma unroll
            for (int q = 0; q < 4; q++) accx[mi][a][q] = 0.f;
    }

#pragma unroll 1
    for (int c = 0; c < TT * 10; ++c) {
        // chunk c was the only outstanding group -> drain it; barrier publishes
        // it CTA-wide AND proves slot (c+1)&1 (read in iter c-1) is free.
        asm volatile("cp.async.wait_group 0;" ::: "memory");
        __syncthreads();
        issue(c + 1);  // overlaps with compute of chunk c

        const int t = c / 10, cm = c % 10, pair = cm / 5, kc = cm % 5;
        const int p = t & 1;
        const uint32_t bbase = smb + RING_OFF + (uint32_t)(c & 1) * 49152u;
        const uint32_t abase = smb + APAN_OFF + (uint32_t)p * 40960u + kc * 8192u;
        const bool isx = (kc == 4);

#pragma unroll
        for (int q = 0; q < 4; q++) {
            uint32_t afr[2][4];
#pragma unroll
            for (int mi = 0; mi < 2; mi++) {
                int r = arow + mi * 16, cc = q * 2 + asel;
                ldm4(afr[mi], abase + r * 128 + ((cc ^ (r & 7)) << 4));
            }
#pragma unroll
            for (int pp = 0; pp < 3; pp++) {
                int r = brow0 + pp * 16, cc = q * 2 + bsel;
                uint32_t v[4];
                ldm4(v, bbase + r * 128 + ((cc ^ (r & 7)) << 4));
                if (pp < 2 || !isx) {
#pragma unroll
                    for (int mi = 0; mi < 2; mi++) {
                        mmaf16(acc[mi][2 * pp], afr[mi], v[0], v[1]);
                        mmaf16(acc[mi][2 * pp + 1], afr[mi], v[2], v[3]);
                    }
                } else {
#pragma unroll
                    for (int mi = 0; mi < 2; mi++) {
                        mmaf16(accx[mi][0], afr[mi], v[0], v[1]);
                        mmaf16(accx[mi][1], afr[mi], v[2], v[3]);
                    }
                }
            }
        }

        if (isx) {
            // ---- fused epilogue for this pair (warp-local; j = pair*128+wn*16+..) ----
            // NOTE: hrd/hwr are plain BYTE OFFSETS (used with generic pointer sm);
            // R10's bug was adding smb here too (double-counting the shared base).
            const int jbase = pair * 128 + wn * 16;
            const uint32_t hrd = APAN_OFF + (uint32_t)p * 40960u;
            const uint32_t hwr = APAN_OFF + (uint32_t)(p ^ 1) * 40960u;
#pragma unroll
            for (int mi = 0; mi < 2; mi++)
#pragma unroll
                for (int rs = 0; rs < 2; rs++) {
                    const int m = wm * 32 + mi * 16 + rs * 8 + tr;
                    const float prev = s_prev[p * 64 + m];
                    float dacc = 0.f;
#pragma unroll
                    for (int o = 0; o < 2; o++) {
                        const int j0 = jbase + o * 8 + 2 * tq;
                        const int cc = (j0 & 63) >> 3;
                        const uint32_t hoff = (uint32_t)((j0 >> 6) * 8192 + m * 128 +
                                              ((cc ^ (m & 7)) << 4) + (j0 & 7) * 2);
                        uint32_t hw = *(const uint32_t*)(sm + hrd + hoff);
                        uint32_t lw = *(const uint32_t*)&s_lo[m * 256 + j0];
                        float hn2[2];
#pragma unroll
                        for (int i = 0; i < 2; i++) {
                            const float* e = &s_epi[(j0 + i) * 8];
                            float cz = acc[mi][0 + o][rs * 2 + i] + prev * e[0] + e[3];
                            float cr = acc[mi][2 + o][rs * 2 + i] + prev * e[1] + e[4];
                            float cx = accx[mi][o][rs * 2 + i] + prev * e[2] + e[5];
                            float ch = acc[mi][4 + o][rs * 2 + i] + e[6];
                            float z = sigf(cz), r = sigf(cr);
                            float cand = tanhfast(cx + r * ch);
                            float hold = hfpart(hw, i) + hfpart(lw, i);
                            float hn = z * hold + (1.f - z) * cand;
                            dacc += hn * e[7];
                            hn2[i] = hn;
                        }
                        __half h0 = __float2half_rn(hn2[0]);
                        __half h1 = __float2half_rn(hn2[1]);
                        __half l0 = __float2half_rn(hn2[0] - __half2float(h0));
                        __half l1 = __float2half_rn(hn2[1] - __half2float(h1));
                        *(uint32_t*)(sm + hwr + hoff) =
                            (uint32_t)__half_as_ushort(h0) |
                            ((uint32_t)__half_as_ushort(h1) << 16);
                        *(uint32_t*)&s_lo[m * 256 + j0] =
                            (uint32_t)__half_as_ushort(l0) |
                            ((uint32_t)__half_as_ushort(l1) << 16);
                    }
                    dacc += __shfl_xor_sync(0xffffffffu, dacc, 1);
                    dacc += __shfl_xor_sync(0xffffffffu, dacc, 2);
                    if (tq == 0) atomicAdd(&s_dacc[m], dacc);
                }
            // reset accumulators for the next pair
#pragma unroll
            for (int mi = 0; mi < 2; mi++) {
#pragma unroll
                for (int a = 0; a < 6; a++)
#pragma unroll
                    for (int q = 0; q < 4; q++) acc[mi][a][q] = 0.f;
#pragma unroll
                for (int a = 0; a < 2; a++)
#pragma unroll
                    for (int q = 0; q < 4; q++) accx[mi][a][q] = 0.f;
            }
        }

        if (cm == 9) {
            __syncthreads();  // all epilogue atomics for step t done
            if (tid < 64) {
                float v = s_dacc[tid] + db[0];
                s_prev[((t + 1) & 1) * 64 + tid] = v;
                out[(size_t)(b0 + tid) * TT + t] = v;
                s_dacc[tid] = 0.f;
            }
            // next consumers of s_prev/s_dacc sit behind the per-chunk barriers
        }
    }
}

// ---------------- launch ----------------
extern "C" void kernel_launch(void* const* d_in, const int* in_sizes, int n_in,
                              void* d_out, int out_size) {
    const float* feat  = (const float*)d_in[0];
    const float* hs0   = (const float*)d_in[1];
    const float* inp0  = (const float*)d_in[2];
    const float* Kw    = (const float*)d_in[3];
    const float* Rw    = (const float*)d_in[4];
    const float* ibias = (const float*)d_in[5];
    const float* rbias = (const float*)d_in[6];
    const float* dw    = (const float*)d_in[7];
    const float* db    = (const float*)d_in[8];
    float* out = (float*)d_out;

    cudaFuncSetAttribute(scan_kernel, cudaFuncAttributeMaxDynamicSharedMemorySize,
                         SMEM_TOTAL);

    size_t nf = (size_t)BB * TT * FF;
    prep_feat<<<(unsigned)((nf + 255) / 256), 256>>>(feat);
    prep_W<<<(10 * 384 * 64 + 255) / 256, 256>>>(Kw, Rw);
    prep_epi<<<1, 256>>>(Kw, ibias, rbias, dw);

    scan_kernel<<<128, 512, SMEM_TOTAL>>>(hs0, inp0, db, out);
}

// round 13
// speedup vs baseline: 1.5729x; 1.1654x over previous
#include <cuda_runtime.h>
#include <cuda_fp16.h>
#include <cstdint>

#define BB 8192
#define TT 96
#define FF 64
#define HH 256

// ---------------- static device buffers ----------------
// Dense weights: [10 chunks][384 rows][64 k] fp16. chunk = pair*5+kc.
// row d = blk_l*48 + slot; j = pair*128 + blk_l*16 + (slot%16);
// slot/16: 0=z,1=r,2=hh(kc<4)/xh(kc==4). k = kc*64+kk (kc<4: Rw; kc==4: Kw[1+kk]).
// blk_l == wn: each wn warp-pair consumes rows [wn*48, wn*48+48).
__device__ __align__(256) __half g_W[10 * 384 * 64];
__device__ __align__(256) __half g_f16[(size_t)BB * TT * FF];  // features fp16
__device__ float g_epi[HH * 8];  // {k0z,k0r,k0h,bz,br,bxh,bhh,dw}

// ---------------- helpers ----------------
static __device__ __forceinline__ uint32_t smem_u32(const void* p) {
    uint32_t a;
    asm("{ .reg .u64 t; cvta.to.shared.u64 t, %1; cvt.u32.u64 %0, t; }"
        : "=r"(a) : "l"(p));
    return a;
}
static __device__ __forceinline__ void cpasync16(uint32_t dst, const void* src) {
    asm volatile("cp.async.cg.shared.global [%0], [%1], 16;"
                 :: "r"(dst), "l"(src) : "memory");
}
static __device__ __forceinline__ void ldm4(uint32_t* d, uint32_t a) {
    asm volatile("ldmatrix.sync.aligned.m8n8.x4.shared.b16 {%0,%1,%2,%3}, [%4];"
                 : "=r"(d[0]), "=r"(d[1]), "=r"(d[2]), "=r"(d[3]) : "r"(a));
}
static __device__ __forceinline__ void mmaf16(float* c, const uint32_t* a,
                                              uint32_t b0, uint32_t b1) {
    asm volatile(
        "mma.sync.aligned.m16n8k16.row.col.f32.f16.f16.f32 "
        "{%0,%1,%2,%3},{%4,%5,%6,%7},{%8,%9},{%0,%1,%2,%3};"
        : "+f"(c[0]), "+f"(c[1]), "+f"(c[2]), "+f"(c[3])
        : "r"(a[0]), "r"(a[1]), "r"(a[2]), "r"(a[3]), "r"(b0), "r"(b1));
}
__device__ __forceinline__ float sigf(float x) {
    return __fdividef(1.0f, 1.0f + __expf(-x));
}
__device__ __forceinline__ float tanhfast(float x) {
    return 1.0f - __fdividef(2.0f, __expf(2.0f * x) + 1.0f);
}
__device__ __forceinline__ float hfpart(uint32_t w, int hi) {
    __half_raw r;
    r.x = hi ? (unsigned short)(w >> 16) : (unsigned short)(w & 0xffff);
    return __half2float(__half(r));
}

// ---------------- prep kernels ----------------
__global__ void prep_feat(const float* __restrict__ f) {
    size_t i = (size_t)blockIdx.x * 256 + threadIdx.x;
    if (i >= (size_t)BB * TT * FF) return;
    g_f16[i] = __float2half_rn(f[i]);
}

__global__ void prep_W(const float* __restrict__ Kw, const float* __restrict__ Rw) {
    int idx = blockIdx.x * 256 + threadIdx.x;
    if (idx >= 10 * 384 * 64) return;
    int kk = idx & 63;
    int d = (idx >> 6) % 384;
    int c10 = idx / (384 * 64);
    int pair = c10 / 5, kc = c10 % 5;
    int blk_l = d / 48, slot = d % 48;
    int gate = slot >> 4, jl = slot & 15;
    int j = pair * 128 + blk_l * 16 + jl;
    int off = (gate == 0) ? 0 : (gate == 1) ? 256 : 512;
    float v;
    if (kc < 4) v = Rw[(kc * 64 + kk) * 768 + off + j];
    else        v = Kw[(1 + kk) * 768 + off + j];
    g_W[idx] = __float2half_rn(v);
}

__global__ void prep_epi(const float* __restrict__ Kw, const float* __restrict__ ib,
                         const float* __restrict__ rb, const float* __restrict__ dw) {
    int j = threadIdx.x;
    float* e = &g_epi[j * 8];
    e[0] = Kw[j];
    e[1] = Kw[256 + j];
    e[2] = Kw[512 + j];
    e[3] = ib[j] + rb[j];
    e[4] = ib[256 + j] + rb[256 + j];
    e[5] = ib[512 + j];
    e[6] = rb[512 + j];
    e[7] = dw[j];
}

// ---------------- persistent scan kernel ----------------
// SMEM: ring 2 slots x [8 wn-pairs x 6KB] = 96K | Apanels 2x5x8K | h_lo 64x264 halfs
//       | epi 8K | prev 2x64f | dacc 64f
#define RING_OFF 0
#define APAN_OFF 98304
#define LO_OFF   180224
#define LOSTRIDE 264
#define EPI_OFF  214016
#define PREV_OFF 222208
#define DACC_OFF 222720
#define SMEM_TOTAL 222976

__global__ __launch_bounds__(512, 1) void scan_kernel(
    const float* __restrict__ hs0, const float* __restrict__ inp0,
    const float* __restrict__ db, float* __restrict__ out) {
    extern __shared__ char sm[];
    const uint32_t smb = smem_u32(sm);
    float* s_epi = (float*)(sm + EPI_OFF);
    float* s_prev = (float*)(sm + PREV_OFF);   // [2][64]
    float* s_dacc = (float*)(sm + DACC_OFF);   // [64]
    __half* s_lo = (__half*)(sm + LO_OFF);     // [64][LOSTRIDE]

    const int tid = threadIdx.x, lane = tid & 31, wid = tid >> 5;
    const int b0 = blockIdx.x * 64;
    const int wm = wid >> 3, wn = wid & 7;     // 2m x 8n warps; warp = 32m x 48n
    const int tq = lane & 3, tr = lane >> 2;

    const int arow = wm * 32 + (lane & 15), asel = lane >> 4;
    const int bsub = lane >> 3, bl8 = lane & 7;
    const int brow0 = ((bsub >> 1) << 3) + bl8, bsel = bsub & 1;  // LOCAL to pair tile

    // ---- per-pair weight loader: warps wm0/wm1 of pair wn each load 24 rows
    //      of their pair's 48x64 tile. feat(t+1) piggybacks on chunk c%10==8
    //      (issued by ALL threads; CTA-visible after the step-end barrier). ----
    auto issue = [&](int c) {
        if (c >= TT * 10) return;
        const int cm = c % 10;
        const uint32_t pbase = smb + RING_OFF + (uint32_t)(c & 1) * 49152u + wn * 6144u;
        const __half* wsrc = &g_W[cm * (384 * 64) + wn * 48 * 64];
#pragma unroll
        for (int i = 0; i < 6; i++) {
            int u = lane + i * 32;
            int r = wm * 24 + (u >> 3), cc = u & 7;
            cpasync16(pbase + r * 128 + ((cc ^ (r & 7)) << 4), wsrc + r * 64 + cc * 8);
        }
        if (cm == 8) {
            int tn = c / 10 + 1;
            if (tn < TT) {
                int r = tid >> 3, cc = tid & 7;
                uint32_t fb = smb + APAN_OFF + (uint32_t)(tn & 1) * 40960u + 4u * 8192u;
                cpasync16(fb + r * 128 + ((cc ^ (r & 7)) << 4),
                          &g_f16[((size_t)(b0 + r) * TT + tn) * FF + cc * 8]);
            }
        }
        asm volatile("cp.async.commit_group;" ::: "memory");
    };

    issue(0);

    // ---- init: h -> panels[0] + lo ; feat(0) ; epi ; prev ----
    for (int idx = tid; idx < 64 * 256; idx += 512) {
        int m = idx >> 8, j = idx & 255;
        float v = hs0[(size_t)(b0 + m) * HH + j];
        __half hi = __float2half_rn(v);
        s_lo[m * LOSTRIDE + j] = __float2half_rn(v - __half2float(hi));
        int cc = (j & 63) >> 3;
        *(__half*)(sm + APAN_OFF + (j >> 6) * 8192 + m * 128 +
                   ((cc ^ (m & 7)) << 4) + (j & 7) * 2) = hi;
    }
    {   // feat t=0
        int r = tid >> 3, cc = tid & 7;
        *(uint4*)(sm + APAN_OFF + 4 * 8192 + r * 128 + ((cc ^ (r & 7)) << 4)) =
            *(const uint4*)&g_f16[((size_t)(b0 + r) * TT) * FF + cc * 8];
    }
    for (int i = tid; i < 2048; i += 512) s_epi[i] = g_epi[i];
    if (tid < 64) {
        s_prev[tid] = inp0[b0 + tid];
        s_dacc[tid] = 0.f;
    }
    __syncthreads();

    float acc[2][6][4], accx[2][2][4];
#pragma unroll
    for (int mi = 0; mi < 2; mi++) {
#pragma unroll
        for (int a = 0; a < 6; a++)
#pragma unroll
            for (int q = 0; q < 4; q++) acc[mi][a][q] = 0.f;
#pragma unroll
        for (int a = 0; a < 2; a++)
#pragma unroll
            for (int q = 0; q < 4; q++) accx[mi][a][q] = 0.f;
    }

#pragma unroll 1
    for (int c = 0; c < TT * 10; ++c) {
        // Each thread drains its own group (chunk c's B-half, + feat at cm8),
        // then the 64-thread pair barrier: (a) publishes both halves of the
        // pair's B tile warp-pair-wide, (b) proves both warps finished chunk
        // c-1 so slot (c+1)&1 is recyclable by issue(c+1) below.
        asm volatile("cp.async.wait_group 0;" ::: "memory");
        asm volatile("bar.sync %0, 64;" :: "r"(1 + wn) : "memory");
        issue(c + 1);

        const int t = c / 10, cm = c % 10, pair = cm / 5, kc = cm % 5;
        const int p = t & 1;
        const uint32_t bbase = smb + RING_OFF + (uint32_t)(c & 1) * 49152u + wn * 6144u;
        const uint32_t abase = smb + APAN_OFF + (uint32_t)p * 40960u + kc * 8192u;
        const bool isx = (kc == 4);

#pragma unroll
        for (int q = 0; q < 4; q++) {
            uint32_t afr[2][4];
#pragma unroll
            for (int mi = 0; mi < 2; mi++) {
                int r = arow + mi * 16, cc = q * 2 + asel;
                ldm4(afr[mi], abase + r * 128 + ((cc ^ (r & 7)) << 4));
            }
#pragma unroll
            for (int pp = 0; pp < 3; pp++) {
                int r = brow0 + pp * 16, cc = q * 2 + bsel;
                uint32_t v[4];
                ldm4(v, bbase + r * 128 + ((cc ^ (r & 7)) << 4));
                if (pp < 2 || !isx) {
#pragma unroll
                    for (int mi = 0; mi < 2; mi++) {
                        mmaf16(acc[mi][2 * pp], afr[mi], v[0], v[1]);
                        mmaf16(acc[mi][2 * pp + 1], afr[mi], v[2], v[3]);
                    }
                } else {
#pragma unroll
                    for (int mi = 0; mi < 2; mi++) {
                        mmaf16(accx[mi][0], afr[mi], v[0], v[1]);
                        mmaf16(accx[mi][1], afr[mi], v[2], v[3]);
                    }
                }
            }
        }

        if (isx) {
            // ---- fused epilogue for this pair. All reads are parity p (old h,
            // warp-local rows/cols for lo), all writes parity p^1 / s_lo's own
            // slice -> no cross-warp hazard until the step-end CTA barriers.
            const int jbase = pair * 128 + wn * 16;
            const uint32_t hrd = APAN_OFF + (uint32_t)p * 40960u;        // byte offs
            const uint32_t hwr = APAN_OFF + (uint32_t)(p ^ 1) * 40960u;  // byte offs
#pragma unroll
            for (int mi = 0; mi < 2; mi++)
#pragma unroll
                for (int rs = 0; rs < 2; rs++) {
                    const int m = wm * 32 + mi * 16 + rs * 8 + tr;
                    const float prev = s_prev[p * 64 + m];
                    float dacc = 0.f;
#pragma unroll
                    for (int o = 0; o < 2; o++) {
                        const int j0 = jbase + o * 8 + 2 * tq;
                        const int cc = (j0 & 63) >> 3;
                        const uint32_t hoff = (uint32_t)((j0 >> 6) * 8192 + m * 128 +
                                              ((cc ^ (m & 7)) << 4) + (j0 & 7) * 2);
                        uint32_t hw = *(const uint32_t*)(sm + hrd + hoff);
                        uint32_t lw = *(const uint32_t*)&s_lo[m * LOSTRIDE + j0];
                        float hn2[2];
#pragma unroll
                        for (int i = 0; i < 2; i++) {
                            const float* e = &s_epi[(j0 + i) * 8];
                            float cz = acc[mi][0 + o][rs * 2 + i] + prev * e[0] + e[3];
                            float cr = acc[mi][2 + o][rs * 2 + i] + prev * e[1] + e[4];
                            float cx = accx[mi][o][rs * 2 + i] + prev * e[2] + e[5];
                            float ch = acc[mi][4 + o][rs * 2 + i] + e[6];
                            float z = sigf(cz), r = sigf(cr);
                            float cand = tanhfast(cx + r * ch);
                            float hold = hfpart(hw, i) + hfpart(lw, i);
                            float hn = z * hold + (1.f - z) * cand;
                            dacc += hn * e[7];
                            hn2[i] = hn;
                        }
                        __half h0 = __float2half_rn(hn2[0]);
                        __half h1 = __float2half_rn(hn2[1]);
                        __half l0 = __float2half_rn(hn2[0] - __half2float(h0));
                        __half l1 = __float2half_rn(hn2[1] - __half2float(h1));
                        *(uint32_t*)(sm + hwr + hoff) =
                            (uint32_t)__half_as_ushort(h0) |
                            ((uint32_t)__half_as_ushort(h1) << 16);
                        *(uint32_t*)&s_lo[m * LOSTRIDE + j0] =
                            (uint32_t)__half_as_ushort(l0) |
                            ((uint32_t)__half_as_ushort(l1) << 16);
                    }
                    dacc += __shfl_xor_sync(0xffffffffu, dacc, 1);
                    dacc += __shfl_xor_sync(0xffffffffu, dacc, 2);
                    if (tq == 0) atomicAdd(&s_dacc[m], dacc);
                }
            // reset accumulators for the next pair
#pragma unroll
            for (int mi = 0; mi < 2; mi++) {
#pragma unroll
                for (int a = 0; a < 6; a++)
#pragma unroll
                    for (int q = 0; q < 4; q++) acc[mi][a][q] = 0.f;
#pragma unroll
                for (int a = 0; a < 2; a++)
#pragma unroll
                    for (int q = 0; q < 4; q++) accx[mi][a][q] = 0.f;
            }
        }

        if (cm == 9) {
            // CTA barrier #1: all epilogue writes (h parity p^1, dacc atomics)
            // and every thread's feat-group wait (done at cm8) have completed.
            __syncthreads();
            if (tid < 64) {
                float v = s_dacc[tid] + db[0];
                s_prev[((t + 1) & 1) * 64 + tid] = v;
                out[(size_t)(b0 + tid) * TT + t] = v;
                s_dacc[tid] = 0.f;
            }
            // CTA barrier #2: publish prev/dacc before step t+1 consumes them.
            __syncthreads();
        }
    }
}

// ---------------- launch ----------------
extern "C" void kernel_launch(void* const* d_in, const int* in_sizes, int n_in,
                              void* d_out, int out_size) {
    const float* feat  = (const float*)d_in[0];
    const float* hs0   = (const float*)d_in[1];
    const float* inp0  = (const float*)d_in[2];
    const float* Kw    = (const float*)d_in[3];
    const float* Rw    = (const float*)d_in[4];
    const float* ibias = (const float*)d_in[5];
    const float* rbias = (const float*)d_in[6];
    const float* dw    = (const float*)d_in[7];
    const float* db    = (const float*)d_in[8];
    float* out = (float*)d_out;

    cudaFuncSetAttribute(scan_kernel, cudaFuncAttributeMaxDynamicSharedMemorySize,
                         SMEM_TOTAL);

    size_t nf = (size_t)BB * TT * FF;
    prep_feat<<<(unsigned)((nf + 255) / 256), 256>>>(feat);
    prep_W<<<(10 * 384 * 64 + 255) / 256, 256>>>(Kw, Rw);
    prep_epi<<<1, 256>>>(Kw, ibias, rbias, dw);

    scan_kernel<<<128, 512, SMEM_TOTAL>>>(hs0, inp0, db, out);
}

// round 14
// speedup vs baseline: 1.6546x; 1.0520x over previous
#include <cuda_runtime.h>
#include <cuda_fp16.h>
#include <cstdint>

#define BB 8192
#define TT 96
#define FF 64
#define HH 256

// ---------------- static device buffers ----------------
// Dense weights: [10 chunks][384 rows][64 k] fp16. chunk = pair*5+kc.
// row d = blk_l*48 + slot; j = pair*128 + blk_l*16 + (slot%16);
// slot/16: 0=z,1=r,2=hh(kc<4)/xh(kc==4). k = kc*64+kk (kc<4: Rw; kc==4: Kw[1+kk]).
// blk_l == wn: each wn warp-pair consumes rows [wn*48, wn*48+48).
__device__ __align__(256) __half g_W[10 * 384 * 64];
__device__ __align__(256) __half g_f16[(size_t)BB * TT * FF];  // features fp16
__device__ float g_epi[HH * 8];  // {k0z,k0r,k0h,bz,br,bxh,bhh,dw}

// ---------------- helpers ----------------
static __device__ __forceinline__ uint32_t smem_u32(const void* p) {
    uint32_t a;
    asm("{ .reg .u64 t; cvta.to.shared.u64 t, %1; cvt.u32.u64 %0, t; }"
        : "=r"(a) : "l"(p));
    return a;
}
static __device__ __forceinline__ void cpasync16(uint32_t dst, const void* src) {
    asm volatile("cp.async.cg.shared.global [%0], [%1], 16;"
                 :: "r"(dst), "l"(src) : "memory");
}
static __device__ __forceinline__ void ldm4(uint32_t* d, uint32_t a) {
    asm volatile("ldmatrix.sync.aligned.m8n8.x4.shared.b16 {%0,%1,%2,%3}, [%4];"
                 : "=r"(d[0]), "=r"(d[1]), "=r"(d[2]), "=r"(d[3]) : "r"(a));
}
static __device__ __forceinline__ void mmaf16(float* c, const uint32_t* a,
                                              uint32_t b0, uint32_t b1) {
    asm volatile(
        "mma.sync.aligned.m16n8k16.row.col.f32.f16.f16.f32 "
        "{%0,%1,%2,%3},{%4,%5,%6,%7},{%8,%9},{%0,%1,%2,%3};"
        : "+f"(c[0]), "+f"(c[1]), "+f"(c[2]), "+f"(c[3])
        : "r"(a[0]), "r"(a[1]), "r"(a[2]), "r"(a[3]), "r"(b0), "r"(b1));
}
static __device__ __forceinline__ float tanha(float x) {
    float y;
    asm("tanh.approx.f32 %0, %1;" : "=f"(y) : "f"(x));
    return y;
}
// sigmoid via MUFU.TANH: 1 MUFU instead of 2 (ex2+rcp)
__device__ __forceinline__ float sigf(float x) {
    return fmaf(tanha(0.5f * x), 0.5f, 0.5f);
}
// accurate tanh for the candidate (protects error budget)
__device__ __forceinline__ float tanhfast(float x) {
    return 1.0f - __fdividef(2.0f, __expf(2.0f * x) + 1.0f);
}
__device__ __forceinline__ float hfpart(uint32_t w, int hi) {
    __half_raw r;
    r.x = hi ? (unsigned short)(w >> 16) : (unsigned short)(w & 0xffff);
    return __half2float(__half(r));
}

// ---------------- prep kernels ----------------
__global__ void prep_feat(const float* __restrict__ f) {
    size_t i = (size_t)blockIdx.x * 256 + threadIdx.x;
    if (i >= (size_t)BB * TT * FF) return;
    g_f16[i] = __float2half_rn(f[i]);
}

__global__ void prep_W(const float* __restrict__ Kw, const float* __restrict__ Rw) {
    int idx = blockIdx.x * 256 + threadIdx.x;
    if (idx >= 10 * 384 * 64) return;
    int kk = idx & 63;
    int d = (idx >> 6) % 384;
    int c10 = idx / (384 * 64);
    int pair = c10 / 5, kc = c10 % 5;
    int blk_l = d / 48, slot = d % 48;
    int gate = slot >> 4, jl = slot & 15;
    int j = pair * 128 + blk_l * 16 + jl;
    int off = (gate == 0) ? 0 : (gate == 1) ? 256 : 512;
    float v;
    if (kc < 4) v = Rw[(kc * 64 + kk) * 768 + off + j];
    else        v = Kw[(1 + kk) * 768 + off + j];
    g_W[idx] = __float2half_rn(v);
}

__global__ void prep_epi(const float* __restrict__ Kw, const float* __restrict__ ib,
                         const float* __restrict__ rb, const float* __restrict__ dw) {
    int j = threadIdx.x;
    float* e = &g_epi[j * 8];
    e[0] = Kw[j];
    e[1] = Kw[256 + j];
    e[2] = Kw[512 + j];
    e[3] = ib[j] + rb[j];
    e[4] = ib[256 + j] + rb[256 + j];
    e[5] = ib[512 + j];
    e[6] = rb[512 + j];
    e[7] = dw[j];
}

// ---------------- persistent scan kernel ----------------
// SMEM: ring 2 slots x [8 wn-pairs x 6KB] = 96K | Apanels 2x5x8K | h_lo 64x264 halfs
//       | epi 8K | prev 2x64f | dacc 64f
#define RING_OFF 0
#define APAN_OFF 98304
#define LO_OFF   180224
#define LOSTRIDE 264
#define EPI_OFF  214016
#define PREV_OFF 222208
#define DACC_OFF 222720
#define SMEM_TOTAL 222976

__global__ __launch_bounds__(512, 1) void scan_kernel(
    const float* __restrict__ hs0, const float* __restrict__ inp0,
    const float* __restrict__ db, float* __restrict__ out) {
    extern __shared__ char sm[];
    const uint32_t smb = smem_u32(sm);
    float* s_epi = (float*)(sm + EPI_OFF);
    float* s_prev = (float*)(sm + PREV_OFF);   // [2][64]
    float* s_dacc = (float*)(sm + DACC_OFF);   // [64]
    __half* s_lo = (__half*)(sm + LO_OFF);     // [64][LOSTRIDE]

    const int tid = threadIdx.x, lane = tid & 31, wid = tid >> 5;
    const int b0 = blockIdx.x * 64;
    const int wm = wid >> 3, wn = wid & 7;     // 2m x 8n warps; warp = 32m x 48n
    const int tq = lane & 3, tr = lane >> 2;

    const int arow = wm * 32 + (lane & 15), asel = lane >> 4;
    const int bsub = lane >> 3, bl8 = lane & 7;
    const int brow0 = ((bsub >> 1) << 3) + bl8, bsel = bsub & 1;  // LOCAL to pair tile

    // ---- per-pair weight loader: warps wm0/wm1 of pair wn each load 24 rows
    //      of their pair's 48x64 tile. feat(t+1) piggybacks on chunk c%10==8. ----
    auto issue = [&](int c) {
        if (c >= TT * 10) return;
        const int cm = c % 10;
        const uint32_t pbase = smb + RING_OFF + (uint32_t)(c & 1) * 49152u + wn * 6144u;
        const __half* wsrc = &g_W[cm * (384 * 64) + wn * 48 * 64];
#pragma unroll
        for (int i = 0; i < 6; i++) {
            int u = lane + i * 32;
            int r = wm * 24 + (u >> 3), cc = u & 7;
            cpasync16(pbase + r * 128 + ((cc ^ (r & 7)) << 4), wsrc + r * 64 + cc * 8);
        }
        if (cm == 8) {
            int tn = c / 10 + 1;
            if (tn < TT) {
                int r = tid >> 3, cc = tid & 7;
                uint32_t fb = smb + APAN_OFF + (uint32_t)(tn & 1) * 40960u + 4u * 8192u;
                cpasync16(fb + r * 128 + ((cc ^ (r & 7)) << 4),
                          &g_f16[((size_t)(b0 + r) * TT + tn) * FF + cc * 8]);
            }
        }
        asm volatile("cp.async.commit_group;" ::: "memory");
    };

    issue(0);

    // ---- init: h -> panels[0] + lo ; feat(0) ; epi ; prev ----
    for (int idx = tid; idx < 64 * 256; idx += 512) {
        int m = idx >> 8, j = idx & 255;
        float v = hs0[(size_t)(b0 + m) * HH + j];
        __half hi = __float2half_rn(v);
        s_lo[m * LOSTRIDE + j] = __float2half_rn(v - __half2float(hi));
        int cc = (j & 63) >> 3;
        *(__half*)(sm + APAN_OFF + (j >> 6) * 8192 + m * 128 +
                   ((cc ^ (m & 7)) << 4) + (j & 7) * 2) = hi;
    }
    {   // feat t=0
        int r = tid >> 3, cc = tid & 7;
        *(uint4*)(sm + APAN_OFF + 4 * 8192 + r * 128 + ((cc ^ (r & 7)) << 4)) =
            *(const uint4*)&g_f16[((size_t)(b0 + r) * TT) * FF + cc * 8];
    }
    for (int i = tid; i < 2048; i += 512) s_epi[i] = g_epi[i];
    if (tid < 64) {
        s_prev[tid] = inp0[b0 + tid];
        s_dacc[tid] = 0.f;
    }
    __syncthreads();

    float acc[2][6][4], accx[2][2][4];
#pragma unroll
    for (int mi = 0; mi < 2; mi++) {
#pragma unroll
        for (int a = 0; a < 6; a++)
#pragma unroll
            for (int q = 0; q < 4; q++) acc[mi][a][q] = 0.f;
#pragma unroll
        for (int a = 0; a < 2; a++)
#pragma unroll
            for (int q = 0; q < 4; q++) accx[mi][a][q] = 0.f;
    }

#pragma unroll 1
    for (int c = 0; c < TT * 10; ++c) {
        // Drain own group; 64-thread pair barrier publishes the pair's B tile
        // and proves slot (c+1)&1 is recyclable.
        asm volatile("cp.async.wait_group 0;" ::: "memory");
        asm volatile("bar.sync %0, 64;" :: "r"(1 + wn) : "memory");
        issue(c + 1);

        const int t = c / 10, cm = c % 10, pair = cm / 5, kc = cm % 5;
        const int p = t & 1;
        const uint32_t bbase = smb + RING_OFF + (uint32_t)(c & 1) * 49152u + wn * 6144u;
        const uint32_t abase = smb + APAN_OFF + (uint32_t)p * 40960u + kc * 8192u;
        const bool isx = (kc == 4);

#pragma unroll
        for (int q = 0; q < 4; q++) {
            uint32_t afr[2][4];
#pragma unroll
            for (int mi = 0; mi < 2; mi++) {
                int r = arow + mi * 16, cc = q * 2 + asel;
                ldm4(afr[mi], abase + r * 128 + ((cc ^ (r & 7)) << 4));
            }
#pragma unroll
            for (int pp = 0; pp < 3; pp++) {
                int r = brow0 + pp * 16, cc = q * 2 + bsel;
                uint32_t v[4];
                ldm4(v, bbase + r * 128 + ((cc ^ (r & 7)) << 4));
                if (pp < 2 || !isx) {
#pragma unroll
                    for (int mi = 0; mi < 2; mi++) {
                        mmaf16(acc[mi][2 * pp], afr[mi], v[0], v[1]);
                        mmaf16(acc[mi][2 * pp + 1], afr[mi], v[2], v[3]);
                    }
                } else {
#pragma unroll
                    for (int mi = 0; mi < 2; mi++) {
                        mmaf16(accx[mi][0], afr[mi], v[0], v[1]);
                        mmaf16(accx[mi][1], afr[mi], v[2], v[3]);
                    }
                }
            }
        }

        if (isx) {
            // ---- fused epilogue for this pair ----
            const int jbase = pair * 128 + wn * 16;
            const uint32_t hrd = APAN_OFF + (uint32_t)p * 40960u;        // byte offs
            const uint32_t hwr = APAN_OFF + (uint32_t)(p ^ 1) * 40960u;  // byte offs

            // hoisted epilogue constants: independent of (mi,rs)
            float ev[2][2][8];
#pragma unroll
            for (int o = 0; o < 2; o++)
#pragma unroll
                for (int i = 0; i < 2; i++) {
                    const float* e = &s_epi[(jbase + o * 8 + 2 * tq + i) * 8];
                    float4 u0 = *(const float4*)e;
                    float4 u1 = *(const float4*)(e + 4);
                    ev[o][i][0] = u0.x; ev[o][i][1] = u0.y;
                    ev[o][i][2] = u0.z; ev[o][i][3] = u0.w;
                    ev[o][i][4] = u1.x; ev[o][i][5] = u1.y;
                    ev[o][i][6] = u1.z; ev[o][i][7] = u1.w;
                }

#pragma unroll
            for (int mi = 0; mi < 2; mi++)
#pragma unroll
                for (int rs = 0; rs < 2; rs++) {
                    const int m = wm * 32 + mi * 16 + rs * 8 + tr;
                    const float prev = s_prev[p * 64 + m];
                    float dacc = 0.f;
#pragma unroll
                    for (int o = 0; o < 2; o++) {
                        const int j0 = jbase + o * 8 + 2 * tq;
                        const int cc = (j0 & 63) >> 3;
                        const uint32_t hoff = (uint32_t)((j0 >> 6) * 8192 + m * 128 +
                                              ((cc ^ (m & 7)) << 4) + (j0 & 7) * 2);
                        uint32_t hw = *(const uint32_t*)(sm + hrd + hoff);
                        uint32_t lw = *(const uint32_t*)&s_lo[m * LOSTRIDE + j0];
                        float hn2[2];
#pragma unroll
                        for (int i = 0; i < 2; i++) {
                            const float* e = ev[o][i];
                            float cz = acc[mi][0 + o][rs * 2 + i] + prev * e[0] + e[3];
                            float cr = acc[mi][2 + o][rs * 2 + i] + prev * e[1] + e[4];
                            float cx = accx[mi][o][rs * 2 + i] + prev * e[2] + e[5];
                            float ch = acc[mi][4 + o][rs * 2 + i] + e[6];
                            float z = sigf(cz), r = sigf(cr);
                            float cand = tanhfast(cx + r * ch);
                            float hold = hfpart(hw, i) + hfpart(lw, i);
                            float hn = z * hold + (1.f - z) * cand;
                            dacc += hn * e[7];
                            hn2[i] = hn;
                        }
                        __half h0 = __float2half_rn(hn2[0]);
                        __half h1 = __float2half_rn(hn2[1]);
                        __half l0 = __float2half_rn(hn2[0] - __half2float(h0));
                        __half l1 = __float2half_rn(hn2[1] - __half2float(h1));
                        *(uint32_t*)(sm + hwr + hoff) =
                            (uint32_t)__half_as_ushort(h0) |
                            ((uint32_t)__half_as_ushort(h1) << 16);
                        *(uint32_t*)&s_lo[m * LOSTRIDE + j0] =
                            (uint32_t)__half_as_ushort(l0) |
                            ((uint32_t)__half_as_ushort(l1) << 16);
                    }
                    dacc += __shfl_xor_sync(0xffffffffu, dacc, 1);
                    dacc += __shfl_xor_sync(0xffffffffu, dacc, 2);
                    if (tq == 0) atomicAdd(&s_dacc[m], dacc);
                }
            // reset accumulators for the next pair
#pragma unroll
            for (int mi = 0; mi < 2; mi++) {
#pragma unroll
                for (int a = 0; a < 6; a++)
#pragma unroll
                    for (int q = 0; q < 4; q++) acc[mi][a][q] = 0.f;
#pragma unroll
                for (int a = 0; a < 2; a++)
#pragma unroll
                    for (int q = 0; q < 4; q++) accx[mi][a][q] = 0.f;
            }
        }

        if (cm == 9) {
            // CTA barrier #1: all epilogue writes + dacc atomics done.
            __syncthreads();
            if (tid < 64) {
                float v = s_dacc[tid] + db[0];
                s_prev[((t + 1) & 1) * 64 + tid] = v;
                out[(size_t)(b0 + tid) * TT + t] = v;
                s_dacc[tid] = 0.f;
            }
            // CTA barrier #2: publish prev/dacc before step t+1 consumes them.
            __syncthreads();
        }
    }
}

// ---------------- launch ----------------
extern "C" void kernel_launch(void* const* d_in, const int* in_sizes, int n_in,
                              void* d_out, int out_size) {
    const float* feat  = (const float*)d_in[0];
    const float* hs0   = (const float*)d_in[1];
    const float* inp0  = (const float*)d_in[2];
    const float* Kw    = (const float*)d_in[3];
    const float* Rw    = (const float*)d_in[4];
    const float* ibias = (const float*)d_in[5];
    const float* rbias = (const float*)d_in[6];
    const float* dw    = (const float*)d_in[7];
    const float* db    = (const float*)d_in[8];
    float* out = (float*)d_out;

    cudaFuncSetAttribute(scan_kernel, cudaFuncAttributeMaxDynamicSharedMemorySize,
                         SMEM_TOTAL);

    size_t nf = (size_t)BB * TT * FF;
    prep_feat<<<(unsigned)((nf + 255) / 256), 256>>>(feat);
    prep_W<<<(10 * 384 * 64 + 255) / 256, 256>>>(Kw, Rw);
    prep_epi<<<1, 256>>>(Kw, ibias, rbias, dw);

    scan_kernel<<<128, 512, SMEM_TOTAL>>>(hs0, inp0, db, out);
}